// round 15
// baseline (speedup 1.0000x reference)
#include <cuda_runtime.h>
#include <cstdint>
#include <cstddef>

#define NB 256
#define NN 2048
#define NR 64
#define ND 64
#define NT 8
#define G 64
#define THREADS 1024
#define TCAP 81920
#define TILECAP 2048
#define XST 68

typedef unsigned long long ull;

__device__ unsigned short g_lvl[NB * NN];
__device__ int g_maxlvl;
__device__ unsigned g_flag[NB * NN];
__device__ int g_cnt[128 * 1024];
__device__ int g_scat[128 * 1024];
__device__ int g_tlofs[NT * 1025];
__device__ int g_tasks[NT * TCAP];
__device__ int g_tiledesc[NT * TILECAP];   // (base<<7)|Gr
__device__ int g_ntile[NT];
__device__ int g_tcur[NT];

static __device__ __forceinline__ unsigned ldacq(const unsigned* p) {
    unsigned v; asm volatile("ld.acquire.gpu.u32 %0,[%1];" : "=r"(v) : "l"(p) : "memory"); return v;
}
static __device__ __forceinline__ void strel(unsigned* p, unsigned v) {
    asm volatile("st.release.gpu.u32 [%0],%1;" :: "l"(p), "r"(v) : "memory");
}
static __device__ __forceinline__ void ffma2(ull& d, ull a, ull b) {
    asm("fma.rn.f32x2 %0,%1,%2,%0;" : "+l"(d) : "l"(a), "l"(b));
}
static __device__ __forceinline__ ull add2(ull a, ull b) {
    ull r; asm("add.rn.f32x2 %0,%1,%2;" : "=l"(r) : "l"(a), "l"(b)); return r;
}
static __device__ __forceinline__ ull dup2(float x) {
    ull r; asm("mov.b64 %0,{%1,%1};" : "=l"(r) : "f"(x)); return r;
}
static __device__ __forceinline__ float2 unpk(ull v) {
    float2 f; asm("mov.b64 {%0,%1},%2;" : "=f"(f.x), "=f"(f.y) : "l"(v)); return f;
}
static __device__ __forceinline__ float gelu(float x) {
    return 0.5f * x * (1.0f + erff(x * 0.70710678118654752440f));
}
#define BAR1() asm volatile("bar.sync 1, 512;" ::: "memory")
#define BAR2_ARRIVE() asm volatile("bar.arrive 2, 1024;" ::: "memory")
#define BAR2_SYNC() asm volatile("bar.sync 2, 1024;" ::: "memory")
#define BAR3() asm volatile("bar.sync 3, 512;" ::: "memory")

// -------- init -------------------------------------------------------------
__global__ void k_init(const float* __restrict__ root, float* __restrict__ out) {
    int tid = blockIdx.x * blockDim.x + threadIdx.x;
    int nt = gridDim.x * blockDim.x;
    if (tid == 0) g_maxlvl = 0;
    for (int i = tid; i < NB * NN; i += nt)
        g_flag[i] = ((i & (NN - 1)) < NR) ? 1u : 0u;
    const float4* r4 = (const float4*)root;
    float4* o4 = (float4*)out;
    const int RD4 = NR * ND / 4;
    for (int i = tid; i < NB * RD4; i += nt) {
        int b = i / RD4;
        o4[(size_t)b * (NN * ND / 4) + (i - b * RD4)] = r4[i];
    }
}

// -------- exact longest-path levels ----------------------------------------
__global__ void k_depth(const int* __restrict__ pidx) {
    extern __shared__ unsigned short slvl[];
    const int b = blockIdx.x * 32 + threadIdx.x;
    unsigned short* L = slvl + threadIdx.x * NN;
#pragma unroll
    for (int i = 0; i < NR; i++) L[i] = 0;
    const int2* pp = (const int2*)pidx + (size_t)b * NN;
    unsigned short* gl = g_lvl + (size_t)b * NN;
    int maxl = 0;
    for (int i = NR; i < NN; i += 2) {
        int4 q = *(const int4*)(pp + i);
        int l1 = L[q.x], l2 = L[q.y];
        int la = 1 + (l1 > l2 ? l1 : l2);
        L[i] = (unsigned short)la; gl[i] = (unsigned short)la;
        int l3 = L[q.z], l4 = L[q.w];
        int lb = 1 + (l3 > l4 ? l3 : l4);
        L[i + 1] = (unsigned short)lb; gl[i + 1] = (unsigned short)lb;
        int m = la > lb ? la : lb;
        if (m > maxl) maxl = m;
    }
    atomicMax(&g_maxlvl, maxl);
}

// -------- count / merge / scatter / tiles -----------------------------------
__global__ void k_count(const int* __restrict__ types) {
    __shared__ int cnt[1024];
    const int c = blockIdx.x, ty = c >> 4, slot = c & 15, t = threadIdx.x;
    for (int l = t; l < 1024; l += 256) cnt[l] = 0;
    __syncthreads();
    for (int u = 0; u < 16; u++) {
        const int b = slot * 16 + u;
        for (int i = NR + t; i < NN; i += 256)
            if (types[b * NN + i] == ty)
                atomicAdd(&cnt[g_lvl[b * NN + i]], 1);
    }
    __syncthreads();
    for (int l = t; l < 1024; l += 256) g_cnt[c * 1024 + l] = cnt[l];
}

__global__ void k_merge() {
    __shared__ int sa[1024], sb_[1024];
    const int ty = blockIdx.x, l = threadIdx.x;
    int cs[16]; int tot = 0;
#pragma unroll
    for (int s = 0; s < 16; s++) { cs[s] = g_cnt[(ty * 16 + s) * 1024 + l]; tot += cs[s]; }
    sa[l] = tot;
    __syncthreads();
    int* pin = sa; int* pout = sb_;
    for (int off = 1; off < 1024; off <<= 1) {
        int v = pin[l] + (l >= off ? pin[l - off] : 0);
        pout[l] = v;
        __syncthreads();
        int* tmp = pin; pin = pout; pout = tmp;
    }
    int incl = pin[l];
    int excl = incl - tot;
    g_tlofs[ty * 1025 + l] = excl;
    if (l == 1023) g_tlofs[ty * 1025 + 1024] = incl;
    int run = excl;
#pragma unroll
    for (int s = 0; s < 16; s++) { g_scat[(ty * 16 + s) * 1024 + l] = run; run += cs[s]; }
}

__global__ void k_scatter(const int* __restrict__ types) {
    __shared__ int wr[1024];
    const int c = blockIdx.x, ty = c >> 4, slot = c & 15, t = threadIdx.x;
    for (int l = t; l < 1024; l += 256) wr[l] = g_scat[c * 1024 + l];
    __syncthreads();
    for (int u = 0; u < 16; u++) {
        const int b = slot * 16 + u;
        for (int i = NR + t; i < NN; i += 256)
            if (types[b * NN + i] == ty) {
                int idx = atomicAdd(&wr[g_lvl[b * NN + i]], 1);
                if (idx < TCAP) g_tasks[ty * TCAP + idx] = (b << 11) | i;
            }
    }
}

// per-type tile queue: tiles never span a level
__global__ void k_tiles() {
    const int ty = threadIdx.x;
    if (ty >= NT) return;
    const int ml = g_maxlvl;
    int n = 0;
    for (int l = 1; l <= ml; l++) {
        int s0 = g_tlofs[ty * 1025 + l], s1 = g_tlofs[ty * 1025 + l + 1];
        for (int b = s0; b < s1; b += G) {
            int gr = min(G, s1 - b);
            if (n < TILECAP) g_tiledesc[ty * TILECAP + n] = (b << 7) | gr;
            n++;
        }
    }
    g_ntile[ty] = min(n, TILECAP);
    g_tcur[ty] = 0;
}

// -------- main: warp-specialized pipeline -----------------------------------
#define OFF_W2 16384
#define OFF_XT 24576
#define OFF_HT (OFF_XT + 128 * XST)     // 33280
#define OFF_SC (OFF_HT + 128 * XST)     // 41984 : scratch 6144 ull (48KB)
#define OFF_B1 (OFF_SC + 12288)         // 54272
#define OFF_B2 (OFF_B1 + 128)
#define OFF_IS (OFF_B2 + 64)
#define SMEM_BYTES ((OFF_IS + 288) * 4)

__global__ void __launch_bounds__(THREADS, 1) k_main(
    const float* __restrict__ W1, const float* __restrict__ B1,
    const float* __restrict__ W2, const float* __restrict__ B2,
    const int* __restrict__ pidx, float* __restrict__ out)
{
    extern __shared__ float sm[];
    float* w1s = sm;                   // [i=128][j=128]
    float* w2s = sm + OFF_W2;          // [j=128][d=64]
    float* xT  = sm + OFF_XT;          // [i=128][XST]
    float* hT  = sm + OFF_HT;          // [j=128][XST]
    ull*   scr = (ull*)(sm + OFF_SC);
    float* b1s = sm + OFF_B1;
    float* b2s = sm + OFF_B2;
    int* rowb  = (int*)(sm + OFF_IS);  // 128 (prologue only)
    int* outbf = rowb + 128;           // 2 x 64
    int* GrS   = outbf + 128;          // 2
    int* tidxS = GrS + 2;              // 2

    const int t = threadIdx.x, w = t >> 5, lane = t & 31;
    const int ty = blockIdx.x >> 4;

    {
        const float4* a = (const float4*)(W1 + ty * 16384);
        for (int i = t; i < 4096; i += THREADS) ((float4*)w1s)[i] = a[i];
        const float4* c2 = (const float4*)(W2 + ty * 8192);
        for (int i = t; i < 2048; i += THREADS) ((float4*)w2s)[i] = c2[i];
        if (t < 128) b1s[t] = B1[ty * 128 + t];
        if (t < 64) b2s[t] = B2[ty * 64 + t];
    }
    const int ntile = g_ntile[ty];
    const int* tasks = g_tasks + ty * TCAP;
    const int* tdesc = g_tiledesc + ty * TILECAP;

    // C roles (warps 0..15): warp tile 32j x 32g, k-split 2, thread 4j x 8g
    const int jtC = w & 3, gtC = (w >> 2) & 1, ksC = w >> 3;
    const int j0C = jtC * 32 + (lane >> 2) * 4;
    const int g0C = gtC * 32 + (lane & 3) * 8;
    // D roles (warps 0..15): warp tile 32d x 32g, k-split 4, thread 4d x 8g
    const int d0D = (w & 1) * 32 + (lane >> 2) * 4;
    const int g0D = ((w >> 1) & 1) * 32 + (lane & 3) * 8;
    const int ksD = w >> 2;
    // prologue gather roles
    const int gB = t & 63, cB = t >> 6;
    const int kkB = cB >> 3, d0B = (cB & 7) * 8;
    // pipeline roles (warps 16..31): u -> (g, kk, 16-float chunk)
    const int u = t - 512;
    const int gP = u & 63, kkP = (u >> 6) & 1, huP = u >> 7;

    if (t == 0) tidxS[0] = atomicAdd(&g_tcur[ty], 1);
    __syncthreads();

    // ---- prologue: synchronous setup+gather of tile 0
    {
        int ti = tidxS[0];
        int desc = (ti < ntile) ? tdesc[ti] : 0;
        int Gr = desc & 127, base = desc >> 7;
        if (t == 0) GrS[0] = Gr;
        if (t < 128) {
            int g = t >> 1, kk = t & 1;
            int rb = 0;
            if (g < Gr) {
                int task = tasks[base + g];
                int pos = task & 2047, b = task >> 11;
                int p = pidx[((size_t)b * NN + pos) * 2 + kk];
                rb = (b * NN + p) * ND;
                if (kk == 0) outbf[g] = (b * NN + pos) * ND;
            } else if (kk == 0) outbf[g] = 0;
            rowb[t] = rb;
            const unsigned* fp = &g_flag[((unsigned)rb) >> 6];
            long long it = 0;
            while (!ldacq(fp)) {
                if (++it > (1ll << 22)) break;
                if ((it & 15) == 15) __nanosleep(64);
            }
        }
        __syncthreads();
        {
            float4 va = make_float4(0.f, 0.f, 0.f, 0.f), vb = va;
            if (gB < Gr) {
                const float* src = out + rowb[2 * gB + kkB] + d0B;
                va = *(const float4*)src;
                vb = *(const float4*)(src + 4);
            }
            float* xp = xT + (kkB * 64 + d0B) * XST + gB;
            xp[0 * XST] = va.x; xp[1 * XST] = va.y;
            xp[2 * XST] = va.z; xp[3 * XST] = va.w;
            xp[4 * XST] = vb.x; xp[5 * XST] = vb.y;
            xp[6 * XST] = vb.z; xp[7 * XST] = vb.w;
        }
        __syncthreads();
    }

    int cur = 0;
    for (;;) {
        const int Gr = GrS[cur];
        const int* outb = outbf + cur * 64;

        if (w < 16) {
            // ================= CONSUMER: compute tile k =================
            ull acc[16];
            // ---- C main
            if (ksC == 0) {
#pragma unroll
                for (int q = 0; q < 4; q++) {
                    ull bv = dup2(b1s[j0C + q]);
                    acc[q * 4 + 0] = bv; acc[q * 4 + 1] = bv;
                    acc[q * 4 + 2] = bv; acc[q * 4 + 3] = bv;
                }
            } else {
#pragma unroll
                for (int a = 0; a < 16; a++) acc[a] = 0ull;
            }
            {
                const float* wp = w1s + ksC * 64 * 128 + j0C;
                const float* xp = xT + ksC * 64 * XST + g0C;
#pragma unroll 2
                for (int i = 0; i < 64; i++) {
                    float4 wv = *(const float4*)(wp + i * 128);
                    ulonglong2 xa = *(const ulonglong2*)(xp + i * XST);
                    ulonglong2 xb = *(const ulonglong2*)(xp + i * XST + 4);
                    ull w0 = dup2(wv.x), w1 = dup2(wv.y), w2 = dup2(wv.z), w3 = dup2(wv.w);
                    ffma2(acc[0], xa.x, w0); ffma2(acc[1], xa.y, w0);
                    ffma2(acc[2], xb.x, w0); ffma2(acc[3], xb.y, w0);
                    ffma2(acc[4], xa.x, w1); ffma2(acc[5], xa.y, w1);
                    ffma2(acc[6], xb.x, w1); ffma2(acc[7], xb.y, w1);
                    ffma2(acc[8], xa.x, w2); ffma2(acc[9], xa.y, w2);
                    ffma2(acc[10], xb.x, w2); ffma2(acc[11], xb.y, w2);
                    ffma2(acc[12], xa.x, w3); ffma2(acc[13], xa.y, w3);
                    ffma2(acc[14], xb.x, w3); ffma2(acc[15], xb.y, w3);
                }
                if (ksC == 1) {
                    ull* cp = scr + (w - 8) * 32 + lane;
#pragma unroll
                    for (int a = 0; a < 16; a++) cp[a * 256] = acc[a];
                }
            }
            BAR1();            // C xT reads + partials done
            BAR2_ARRIVE();     // release xT to producers
            // ---- C combine + GELU (warps 0..7)
            if (w < 8) {
                const ull* cp = scr + w * 32 + lane;
#pragma unroll
                for (int a = 0; a < 16; a++) acc[a] = add2(acc[a], cp[a * 256]);
#pragma unroll
                for (int q = 0; q < 4; q++) {
                    float2 f0 = unpk(acc[q * 4 + 0]), f1 = unpk(acc[q * 4 + 1]);
                    float2 f2 = unpk(acc[q * 4 + 2]), f3 = unpk(acc[q * 4 + 3]);
                    float4* hr = (float4*)(hT + (j0C + q) * XST + g0C);
                    hr[0] = make_float4(gelu(f0.x), gelu(f0.y), gelu(f1.x), gelu(f1.y));
                    hr[1] = make_float4(gelu(f2.x), gelu(f2.y), gelu(f3.x), gelu(f3.y));
                }
            }
            BAR1();            // hT ready
            // ---- D main
            if (ksD == 0) {
#pragma unroll
                for (int q = 0; q < 4; q++) {
                    ull bv = dup2(b2s[d0D + q]);
                    acc[q * 4 + 0] = bv; acc[q * 4 + 1] = bv;
                    acc[q * 4 + 2] = bv; acc[q * 4 + 3] = bv;
                }
            } else {
#pragma unroll
                for (int a = 0; a < 16; a++) acc[a] = 0ull;
            }
            {
                const float* wp = w2s + ksD * 32 * 64 + d0D;
                const float* hp = hT + ksD * 32 * XST + g0D;
#pragma unroll 2
                for (int j = 0; j < 32; j++) {
                    float4 wv = *(const float4*)(wp + j * 64);
                    ulonglong2 ha = *(const ulonglong2*)(hp + j * XST);
                    ulonglong2 hb = *(const ulonglong2*)(hp + j * XST + 4);
                    ull w0 = dup2(wv.x), w1 = dup2(wv.y), w2 = dup2(wv.z), w3 = dup2(wv.w);
                    ffma2(acc[0], ha.x, w0); ffma2(acc[1], ha.y, w0);
                    ffma2(acc[2], hb.x, w0); ffma2(acc[3], hb.y, w0);
                    ffma2(acc[4], ha.x, w1); ffma2(acc[5], ha.y, w1);
                    ffma2(acc[6], hb.x, w1); ffma2(acc[7], hb.y, w1);
                    ffma2(acc[8], ha.x, w2); ffma2(acc[9], ha.y, w2);
                    ffma2(acc[10], hb.x, w2); ffma2(acc[11], hb.y, w2);
                    ffma2(acc[12], ha.x, w3); ffma2(acc[13], ha.y, w3);
                    ffma2(acc[14], hb.x, w3); ffma2(acc[15], hb.y, w3);
                }
                if (ksD >= 1) {
                    ull* dp = scr + (ksD - 1) * 128 + (w & 3) * 32 + lane;
#pragma unroll
                    for (int a = 0; a < 16; a++) dp[a * 384] = acc[a];
                }
            }
            BAR1();
            // ---- D combine + STG (warps 0..3)
            if (w < 4) {
                const ull* dp = scr + w * 32 + lane;
#pragma unroll
                for (int s = 0; s < 3; s++)
#pragma unroll
                    for (int a = 0; a < 16; a++)
                        acc[a] = add2(acc[a], dp[s * 128 + a * 384]);
                float od[4][8];
#pragma unroll
                for (int q = 0; q < 4; q++)
#pragma unroll
                    for (int p = 0; p < 4; p++) {
                        float2 f = unpk(acc[q * 4 + p]);
                        od[q][2 * p] = f.x; od[q][2 * p + 1] = f.y;
                    }
#pragma unroll
                for (int e = 0; e < 8; e++) {
                    int g = g0D + e;
                    if (g < Gr)
                        *(float4*)(out + outb[g] + d0D) =
                            make_float4(od[0][e], od[1][e], od[2][e], od[3][e]);
                }
            }
            BAR1();            // row stores done
            if (t < Gr)
                strel(&g_flag[((unsigned)outb[t]) >> 6], 1u);
        } else {
            // ================= PRODUCER: prefetch tile k+1 ===============
            if (t == 512) tidxS[cur ^ 1] = atomicAdd(&g_tcur[ty], 1);
            BAR3();
            int ti = tidxS[cur ^ 1];
            int desc = (ti < ntile) ? tdesc[ti] : 0;
            int Grn = desc & 127, base = desc >> 7;
            float4 v0 = make_float4(0.f, 0.f, 0.f, 0.f), v1 = v0, v2 = v0, v3 = v0;
            if (gP < Grn) {
                int task = tasks[base + gP];
                int pos = task & 2047, b = task >> 11;
                if (u < 64) outbf[(cur ^ 1) * 64 + gP] = (b * NN + pos) * ND;
                int p = pidx[((size_t)b * NN + pos) * 2 + kkP];
                int rb = (b * NN + p) * ND;
                const unsigned* fp = &g_flag[((unsigned)rb) >> 6];
                long long it = 0;
                while (!ldacq(fp)) {
                    if (++it > (1ll << 22)) break;
                    if ((it & 15) == 15) __nanosleep(64);
                }
                const float* src = out + rb + huP * 16;
                v0 = *(const float4*)src;
                v1 = *(const float4*)(src + 4);
                v2 = *(const float4*)(src + 8);
                v3 = *(const float4*)(src + 12);
            }
            if (u == 0) GrS[cur ^ 1] = Grn;
            BAR2_SYNC();       // wait until consumers finish reading xT
            {
                float* xp = xT + (kkP * 64 + huP * 16) * XST + gP;
                xp[0 * XST] = v0.x; xp[1 * XST] = v0.y; xp[2 * XST] = v0.z; xp[3 * XST] = v0.w;
                xp[4 * XST] = v1.x; xp[5 * XST] = v1.y; xp[6 * XST] = v1.z; xp[7 * XST] = v1.w;
                xp[8 * XST] = v2.x; xp[9 * XST] = v2.y; xp[10 * XST] = v2.z; xp[11 * XST] = v2.w;
                xp[12 * XST] = v3.x; xp[13 * XST] = v3.y; xp[14 * XST] = v3.z; xp[15 * XST] = v3.w;
            }
        }
        __syncthreads();       // join: tile k published, tile k+1 staged
        if (GrS[cur ^ 1] == 0) break;
        cur ^= 1;
    }
}

extern "C" void kernel_launch(void* const* d_in, const int* in_sizes, int n_in,
                              void* d_out, int out_size) {
    const float* root = (const float*)d_in[0];
    const float* W1   = (const float*)d_in[1];
    const float* b1   = (const float*)d_in[2];
    const float* W2   = (const float*)d_in[3];
    const float* b2   = (const float*)d_in[4];
    const int*   pidx = (const int*)d_in[5];
    const int*   typ  = (const int*)d_in[6];
    float* out = (float*)d_out;

    cudaFuncSetAttribute(k_depth, cudaFuncAttributeMaxDynamicSharedMemorySize, 32 * NN * 2);
    cudaFuncSetAttribute(k_main, cudaFuncAttributeMaxDynamicSharedMemorySize, SMEM_BYTES);

    k_init<<<256, 256>>>(root, out);
    k_depth<<<8, 32, 32 * NN * 2>>>(pidx);
    k_count<<<128, 256>>>(typ);
    k_merge<<<8, 1024>>>();
    k_scatter<<<128, 256>>>(typ);
    k_tiles<<<1, 8>>>();
    k_main<<<128, THREADS, SMEM_BYTES>>>(W1, b1, W2, b2, pidx, out);
}

// round 16
// speedup vs baseline: 1.5431x; 1.5431x over previous
#include <cuda_runtime.h>
#include <cstdint>
#include <cstddef>

#define NB 256
#define NN 2048
#define NR 64
#define ND 64
#define NT 8
#define G 64
#define THREADS 1024
#define TCAP 81920
#define XST 68
#define SPT 18                    // CTAs per type (8*18 = 144 <= 148 SMs)
#define NCTA (NT * SPT)

typedef unsigned long long ull;

__device__ unsigned short g_lvl[NB * NN];
__device__ int g_maxlvl;
__device__ unsigned g_flag[NB * NN];
__device__ int g_cnt[128 * 1024];
__device__ int g_scat[128 * 1024];
__device__ int g_tlofs[NT * 1025];
__device__ int g_curn[NT * 1024];
__device__ int g_tasks[NT * TCAP];

static __device__ __forceinline__ unsigned ldacq(const unsigned* p) {
    unsigned v; asm volatile("ld.acquire.gpu.u32 %0,[%1];" : "=r"(v) : "l"(p) : "memory"); return v;
}
static __device__ __forceinline__ void strel(unsigned* p, unsigned v) {
    asm volatile("st.release.gpu.u32 [%0],%1;" :: "l"(p), "r"(v) : "memory");
}
static __device__ __forceinline__ void ffma2(ull& d, ull a, ull b) {
    asm("fma.rn.f32x2 %0,%1,%2,%0;" : "+l"(d) : "l"(a), "l"(b));
}
static __device__ __forceinline__ ull add2(ull a, ull b) {
    ull r; asm("add.rn.f32x2 %0,%1,%2;" : "=l"(r) : "l"(a), "l"(b)); return r;
}
static __device__ __forceinline__ ull dup2(float x) {
    ull r; asm("mov.b64 %0,{%1,%1};" : "=l"(r) : "f"(x)); return r;
}
static __device__ __forceinline__ float2 unpk(ull v) {
    float2 f; asm("mov.b64 {%0,%1},%2;" : "=f"(f.x), "=f"(f.y) : "l"(v)); return f;
}
static __device__ __forceinline__ float gelu(float x) {
    return 0.5f * x * (1.0f + erff(x * 0.70710678118654752440f));
}

// -------- init -------------------------------------------------------------
__global__ void k_init(const float* __restrict__ root, float* __restrict__ out) {
    int tid = blockIdx.x * blockDim.x + threadIdx.x;
    int nt = gridDim.x * blockDim.x;
    if (tid == 0) g_maxlvl = 0;
    for (int i = tid; i < NB * NN; i += nt)
        g_flag[i] = ((i & (NN - 1)) < NR) ? 1u : 0u;
    const float4* r4 = (const float4*)root;
    float4* o4 = (float4*)out;
    const int RD4 = NR * ND / 4;
    for (int i = tid; i < NB * RD4; i += nt) {
        int b = i / RD4;
        o4[(size_t)b * (NN * ND / 4) + (i - b * RD4)] = r4[i];
    }
}

// -------- exact longest-path levels ----------------------------------------
__global__ void k_depth(const int* __restrict__ pidx) {
    extern __shared__ unsigned short slvl[];
    const int b = blockIdx.x * 32 + threadIdx.x;
    unsigned short* L = slvl + threadIdx.x * NN;
#pragma unroll
    for (int i = 0; i < NR; i++) L[i] = 0;
    const int2* pp = (const int2*)pidx + (size_t)b * NN;
    unsigned short* gl = g_lvl + (size_t)b * NN;
    int maxl = 0;
    for (int i = NR; i < NN; i += 2) {
        int4 q = *(const int4*)(pp + i);
        int l1 = L[q.x], l2 = L[q.y];
        int la = 1 + (l1 > l2 ? l1 : l2);
        L[i] = (unsigned short)la; gl[i] = (unsigned short)la;
        int l3 = L[q.z], l4 = L[q.w];
        int lb = 1 + (l3 > l4 ? l3 : l4);
        L[i + 1] = (unsigned short)lb; gl[i + 1] = (unsigned short)lb;
        int m = la > lb ? la : lb;
        if (m > maxl) maxl = m;
    }
    atomicMax(&g_maxlvl, maxl);
}

// -------- count / merge / scatter -------------------------------------------
__global__ void k_count(const int* __restrict__ types) {
    __shared__ int cnt[1024];
    const int c = blockIdx.x, ty = c >> 4, slot = c & 15, t = threadIdx.x;
    for (int l = t; l < 1024; l += 256) cnt[l] = 0;
    __syncthreads();
    for (int u = 0; u < 16; u++) {
        const int b = slot * 16 + u;
        for (int i = NR + t; i < NN; i += 256)
            if (types[b * NN + i] == ty)
                atomicAdd(&cnt[g_lvl[b * NN + i]], 1);
    }
    __syncthreads();
    for (int l = t; l < 1024; l += 256) g_cnt[c * 1024 + l] = cnt[l];
}

__global__ void k_merge() {
    __shared__ int sa[1024], sb_[1024];
    const int ty = blockIdx.x, l = threadIdx.x;
    int cs[16]; int tot = 0;
#pragma unroll
    for (int s = 0; s < 16; s++) { cs[s] = g_cnt[(ty * 16 + s) * 1024 + l]; tot += cs[s]; }
    sa[l] = tot;
    __syncthreads();
    int* pin = sa; int* pout = sb_;
    for (int off = 1; off < 1024; off <<= 1) {
        int v = pin[l] + (l >= off ? pin[l - off] : 0);
        pout[l] = v;
        __syncthreads();
        int* tmp = pin; pin = pout; pout = tmp;
    }
    int incl = pin[l];
    int excl = incl - tot;
    g_tlofs[ty * 1025 + l] = excl;
    if (l == 1023) g_tlofs[ty * 1025 + 1024] = incl;
    int run = excl;
#pragma unroll
    for (int s = 0; s < 16; s++) { g_scat[(ty * 16 + s) * 1024 + l] = run; run += cs[s]; }
    g_curn[ty * 1024 + l] = 0;
}

__global__ void k_scatter(const int* __restrict__ types) {
    __shared__ int wr[1024];
    const int c = blockIdx.x, ty = c >> 4, slot = c & 15, t = threadIdx.x;
    for (int l = t; l < 1024; l += 256) wr[l] = g_scat[c * 1024 + l];
    __syncthreads();
    for (int u = 0; u < 16; u++) {
        const int b = slot * 16 + u;
        for (int i = NR + t; i < NN; i += 256)
            if (types[b * NN + i] == ty) {
                int idx = atomicAdd(&wr[g_lvl[b * NN + i]], 1);
                if (idx < TCAP) g_tasks[ty * TCAP + idx] = (b << 11) | i;
            }
    }
}

// -------- main --------------------------------------------------------------
#define OFF_W2 16384
#define OFF_XT 24576
#define OFF_HT (OFF_XT + 128 * XST)     // 33280
#define OFF_SC (OFF_HT + 128 * XST)     // 41984 : scratch 6144 ull (48KB)
#define OFF_B1 (OFF_SC + 12288)         // 54272
#define OFF_B2 (OFF_B1 + 128)
#define OFF_IS (OFF_B2 + 64)
#define SMEM_BYTES ((OFF_IS + 256) * 4)

__global__ void __launch_bounds__(THREADS, 1) k_main(
    const float* __restrict__ W1, const float* __restrict__ B1,
    const float* __restrict__ W2, const float* __restrict__ B2,
    const int* __restrict__ pidx, float* __restrict__ out)
{
    extern __shared__ float sm[];
    float* w1s = sm;                   // [i=128][j=128]
    float* w2s = sm + OFF_W2;          // [j=128][d=64]
    float* xT  = sm + OFF_XT;          // [i=128][XST]
    float* hT  = sm + OFF_HT;          // [j=128][XST]
    ull*   scr = (ull*)(sm + OFF_SC);  // partials: C 16x256, D 16x384
    float* b1s = sm + OFF_B1;
    float* b2s = sm + OFF_B2;
    int* rowb  = (int*)(sm + OFF_IS);  // 128
    int* outb  = rowb + 128;           // 64
    int* sgrab = outb + 64;            // 2 (double-buffered steal)

    const int t = threadIdx.x, w = t >> 5, lane = t & 31;
    const int ty = blockIdx.x / SPT;

    {
        const float4* a = (const float4*)(W1 + ty * 16384);
        for (int i = t; i < 4096; i += THREADS) ((float4*)w1s)[i] = a[i];
        const float4* c2 = (const float4*)(W2 + ty * 8192);
        for (int i = t; i < 2048; i += THREADS) ((float4*)w2s)[i] = c2[i];
        if (t < 128) b1s[t] = B1[ty * 128 + t];
        if (t < 64) b2s[t] = B2[ty * 64 + t];
    }
    const int ml = g_maxlvl;
    const int* tlofs = g_tlofs + ty * 1025;
    const int* tasks = g_tasks + ty * TCAP;
    int* curs = g_curn + ty * 1024;
    __syncthreads();

    // C roles (warps 0..15): warp tile 32j x 32g, k-split 2, thread 4j x 8g
    const int jtC = w & 3, gtC = (w >> 2) & 1, ksC = w >> 3;
    const int j0C = jtC * 32 + (lane >> 2) * 4;
    const int g0C = gtC * 32 + (lane & 3) * 8;
    // D roles (warps 0..15): warp tile 32d x 32g, k-split 4, thread 4d x 8g
    const int d0D = (w & 1) * 32 + (lane >> 2) * 4;
    const int g0D = ((w >> 1) & 1) * 32 + (lane & 3) * 8;
    const int ksD = w >> 2;
    // gather roles: thread = (g, 8-row chunk) -> conflict-free STS columns
    const int gB = t & 63, cB = t >> 6;              // cB 0..15
    const int kkB = cB >> 3, d0B = (cB & 7) * 8;

    for (int l = 1; l <= ml; l++) {
        const int seg0 = tlofs[l], seg1 = tlofs[l + 1];
        if (t == 0) sgrab[0] = atomicAdd(&curs[l], G);
        int cur = 0;
        __syncthreads();
        for (;;) {
            const int base = seg0 + sgrab[cur];
            if (base >= seg1) break;
            const int Gr = min(G, seg1 - base);

            // ---- setup row bases + poll own parent flag (merged, 1 barrier)
            if (t < 2 * G) {
                int g = t >> 1, kk = t & 1;
                int rb = 0;
                if (g < Gr) {
                    int task = tasks[base + g];
                    int pos = task & 2047, b = task >> 11;
                    int p = pidx[((size_t)b * NN + pos) * 2 + kk];
                    rb = (b * NN + p) * ND;
                    if (kk == 0) outb[g] = (b * NN + pos) * ND;
                } else if (kk == 0) outb[g] = -1;
                rowb[t] = rb;
                const unsigned* fp = &g_flag[((unsigned)rb) >> 6];
                long long it = 0;
                while (!ldacq(fp)) {
                    if (++it > (1ll << 22)) break;
                    if ((it & 15) == 15) __nanosleep(64);
                }
            }
            __syncthreads();

            // ---- gather: vector LDG from parent row, conflict-free STS column
            {
                float4 va = make_float4(0.f, 0.f, 0.f, 0.f), vb = va;
                if (gB < Gr) {
                    const float* src = out + rowb[2 * gB + kkB] + d0B;
                    va = *(const float4*)src;
                    vb = *(const float4*)(src + 4);
                }
                float* xp = xT + (kkB * 64 + d0B) * XST + gB;
                xp[0 * XST] = va.x; xp[1 * XST] = va.y;
                xp[2 * XST] = va.z; xp[3 * XST] = va.w;
                xp[4 * XST] = vb.x; xp[5 * XST] = vb.y;
                xp[6 * XST] = vb.z; xp[7 * XST] = vb.w;
            }
            __syncthreads();

            ull acc[16];

            // ---- C: H = gelu(W1^T X + b1), warps 0..15
            if (w < 16) {
                if (ksC == 0) {
#pragma unroll
                    for (int q = 0; q < 4; q++) {
                        ull bv = dup2(b1s[j0C + q]);
                        acc[q * 4 + 0] = bv; acc[q * 4 + 1] = bv;
                        acc[q * 4 + 2] = bv; acc[q * 4 + 3] = bv;
                    }
                } else {
#pragma unroll
                    for (int a = 0; a < 16; a++) acc[a] = 0ull;
                }
                const float* wp = w1s + ksC * 64 * 128 + j0C;
                const float* xp = xT + ksC * 64 * XST + g0C;
#pragma unroll 2
                for (int i = 0; i < 64; i++) {
                    float4 wv = *(const float4*)(wp + i * 128);
                    ulonglong2 xa = *(const ulonglong2*)(xp + i * XST);
                    ulonglong2 xb = *(const ulonglong2*)(xp + i * XST + 4);
                    ull w0 = dup2(wv.x), w1 = dup2(wv.y), w2 = dup2(wv.z), w3 = dup2(wv.w);
                    ffma2(acc[0], xa.x, w0); ffma2(acc[1], xa.y, w0);
                    ffma2(acc[2], xb.x, w0); ffma2(acc[3], xb.y, w0);
                    ffma2(acc[4], xa.x, w1); ffma2(acc[5], xa.y, w1);
                    ffma2(acc[6], xb.x, w1); ffma2(acc[7], xb.y, w1);
                    ffma2(acc[8], xa.x, w2); ffma2(acc[9], xa.y, w2);
                    ffma2(acc[10], xb.x, w2); ffma2(acc[11], xb.y, w2);
                    ffma2(acc[12], xa.x, w3); ffma2(acc[13], xa.y, w3);
                    ffma2(acc[14], xb.x, w3); ffma2(acc[15], xb.y, w3);
                }
                if (ksC == 1) {
                    ull* cp = scr + (w - 8) * 32 + lane;
#pragma unroll
                    for (int a = 0; a < 16; a++) cp[a * 256] = acc[a];
                }
            }
            __syncthreads();
            // ---- C combine + GELU -> hT (warps 0..7)
            if (w < 8) {
                const ull* cp = scr + w * 32 + lane;
#pragma unroll
                for (int a = 0; a < 16; a++) acc[a] = add2(acc[a], cp[a * 256]);
#pragma unroll
                for (int q = 0; q < 4; q++) {
                    float2 f0 = unpk(acc[q * 4 + 0]), f1 = unpk(acc[q * 4 + 1]);
                    float2 f2 = unpk(acc[q * 4 + 2]), f3 = unpk(acc[q * 4 + 3]);
                    float4* hr = (float4*)(hT + (j0C + q) * XST + g0C);
                    hr[0] = make_float4(gelu(f0.x), gelu(f0.y), gelu(f1.x), gelu(f1.y));
                    hr[1] = make_float4(gelu(f2.x), gelu(f2.y), gelu(f3.x), gelu(f3.y));
                }
            }
            __syncthreads();

            // ---- steal prefetch for next tile (idle warp 16) during D
            if (t == 512) sgrab[cur ^ 1] = atomicAdd(&curs[l], G);

            // ---- D: O = W2^T H + b2, warps 0..15
            if (w < 16) {
                if (ksD == 0) {
#pragma unroll
                    for (int q = 0; q < 4; q++) {
                        ull bv = dup2(b2s[d0D + q]);
                        acc[q * 4 + 0] = bv; acc[q * 4 + 1] = bv;
                        acc[q * 4 + 2] = bv; acc[q * 4 + 3] = bv;
                    }
                } else {
#pragma unroll
                    for (int a = 0; a < 16; a++) acc[a] = 0ull;
                }
                const float* wp = w2s + ksD * 32 * 64 + d0D;
                const float* hp = hT + ksD * 32 * XST + g0D;
#pragma unroll 2
                for (int j = 0; j < 32; j++) {
                    float4 wv = *(const float4*)(wp + j * 64);
                    ulonglong2 ha = *(const ulonglong2*)(hp + j * XST);
                    ulonglong2 hb = *(const ulonglong2*)(hp + j * XST + 4);
                    ull w0 = dup2(wv.x), w1 = dup2(wv.y), w2 = dup2(wv.z), w3 = dup2(wv.w);
                    ffma2(acc[0], ha.x, w0); ffma2(acc[1], ha.y, w0);
                    ffma2(acc[2], hb.x, w0); ffma2(acc[3], hb.y, w0);
                    ffma2(acc[4], ha.x, w1); ffma2(acc[5], ha.y, w1);
                    ffma2(acc[6], hb.x, w1); ffma2(acc[7], hb.y, w1);
                    ffma2(acc[8], ha.x, w2); ffma2(acc[9], ha.y, w2);
                    ffma2(acc[10], hb.x, w2); ffma2(acc[11], hb.y, w2);
                    ffma2(acc[12], ha.x, w3); ffma2(acc[13], ha.y, w3);
                    ffma2(acc[14], hb.x, w3); ffma2(acc[15], hb.y, w3);
                }
                if (ksD >= 1) {
                    ull* dp = scr + (ksD - 1) * 128 + (w & 3) * 32 + lane;
#pragma unroll
                    for (int a = 0; a < 16; a++) dp[a * 384] = acc[a];
                }
            }
            __syncthreads();
            // ---- D combine + STG (warps 0..3)
            if (w < 4) {
                const ull* dp = scr + w * 32 + lane;
#pragma unroll
                for (int s = 0; s < 3; s++)
#pragma unroll
                    for (int a = 0; a < 16; a++)
                        acc[a] = add2(acc[a], dp[s * 128 + a * 384]);
                float od[4][8];
#pragma unroll
                for (int q = 0; q < 4; q++)
#pragma unroll
                    for (int p = 0; p < 4; p++) {
                        float2 f = unpk(acc[q * 4 + p]);
                        od[q][2 * p] = f.x; od[q][2 * p + 1] = f.y;
                    }
#pragma unroll
                for (int e = 0; e < 8; e++) {
                    int g = g0D + e;
                    if (g < Gr)
                        *(float4*)(out + outb[g] + d0D) =
                            make_float4(od[0][e], od[1][e], od[2][e], od[3][e]);
                }
            }
            __syncthreads();   // all row stores complete before publish

            // ---- publish
            if (t < Gr)
                strel(&g_flag[((unsigned)outb[t]) >> 6], 1u);
            __syncthreads();   // protect rowb/outb from next tile's setup
            cur ^= 1;
        }
    }
}

extern "C" void kernel_launch(void* const* d_in, const int* in_sizes, int n_in,
                              void* d_out, int out_size) {
    const float* root = (const float*)d_in[0];
    const float* W1   = (const float*)d_in[1];
    const float* b1   = (const float*)d_in[2];
    const float* W2   = (const float*)d_in[3];
    const float* b2   = (const float*)d_in[4];
    const int*   pidx = (const int*)d_in[5];
    const int*   typ  = (const int*)d_in[6];
    float* out = (float*)d_out;

    cudaFuncSetAttribute(k_depth, cudaFuncAttributeMaxDynamicSharedMemorySize, 32 * NN * 2);
    cudaFuncSetAttribute(k_main, cudaFuncAttributeMaxDynamicSharedMemorySize, SMEM_BYTES);

    k_init<<<256, 256>>>(root, out);
    k_depth<<<8, 32, 32 * NN * 2>>>(pidx);
    k_count<<<128, 256>>>(typ);
    k_merge<<<8, 1024>>>();
    k_scatter<<<128, 256>>>(typ);
    k_main<<<NCTA, THREADS, SMEM_BYTES>>>(W1, b1, W2, b2, pidx, out);
}